// round 10
// baseline (speedup 1.0000x reference)
#include <cuda_runtime.h>
#include <stdint.h>

// RasterTriangle_46566035423850 — fully sparse 2D formulation, two-kernel split.
// Prep kernel: per image, extract per-k sparse diff lists of hor (over q) and
// vert (over p) by evaluating the EXACT reference fp32 formula inside
// analytically-located one-pixel ramp windows; also emit a flattened (q,k,dh)
// list for fast base-row builds. Main kernel: per 32-row slice, build base row
// via parallel scatter (shared atomics) + scan, then advance rows incrementally:
//   out[p,:] = out[p-1,:] + prefix_q( sum_{k: dv at p} dv * dH_k )  (usually 0).

#define MAXD 8
#define FLATCAP 512
#define NTHREADS 128
#define NW 4
#define SEG 8

__device__ float g_dhH[512][64][MAXD];
__device__ short g_qH[512][64][MAXD];
__device__ int   g_cntH[512][64];
__device__ float g_dvV[512][64][MAXD];
__device__ short g_pV[512][64][MAXD];
__device__ int   g_cntV[512][64];
__device__ float g_fdh[512][FLATCAP];
__device__ short g_fq[512][FLATCAP];
__device__ short g_fk[512][FLATCAP];
__device__ int   g_nH[512];

// ---------------- prep kernel: one CTA per image ----------------
__global__ void __launch_bounds__(NTHREADS)
prep_kernel(const float* __restrict__ iv0, const float* __restrict__ iv1)
{
    const double PI_D   = 3.141592653589793238462643383279502884;
    const double SIDE_D = (PI_D * 0.5) / 512.0;
    const float  S      = (float)SIDE_D;
    const float  STRIPF = (float)(PI_D * 0.5);
    const float  STOPF  = (float)(PI_D * 0.5 - SIDE_D);
    const float  stepx  = __fdiv_rn(STOPF, 511.0f);
    const float  stepy  = __fdiv_rn(-STOPF, 511.0f);
    const float  invA   = (float)(1.0 / (SIDE_D * SIDE_D));

    __shared__ __align__(16) float xs[64], ys[64];
    __shared__ __align__(16) float s_dhH[64][MAXD], s_dvV[64][MAXD];
    __shared__ __align__(16) short s_qH[64][MAXD], s_pV[64][MAXD];
    __shared__ int s_cntH[64], s_cntV[64];
    __shared__ int off[65];

    const int tid = threadIdx.x;
    const int bid = blockIdx.x;     // imgslot = b*2 + img
    const int img = bid & 1;
    const int b   = bid >> 1;
    const int K   = img ? 32 : 64;

    if (tid < 64) { s_cntH[tid] = 0; s_cntV[tid] = 0; }
    if (tid < 32) {
        const float2 ab = ((const float2*)iv0)[b * 32 + tid];
        xs[tid] = ab.x;  ys[tid] = ab.y;                 // (a0, b0)
    } else if (tid < 64 && img == 0) {
        const float2 ab = ((const float2*)iv1)[b * 32 + (tid - 32)];
        xs[tid] = __fsub_rn(ab.y, STRIPF);               // b1 - STRIP
        ys[tid] = ab.x;                                  // a1
    }
    __syncthreads();

    if (tid < 2 * K) {
        const int k   = tid >> 1;
        const int dim = tid & 1;     // 0 = horizontal(q), 1 = vertical(p)
        const float x = xs[k], y = ys[k];

        float w1lo, w1hi, w2lo, w2hi; int has2;
        if (dim == 0) {
            w1lo = __fdiv_rn(__fsub_rn(x, S), stepx);  w1hi = __fdiv_rn(x, stepx);
            w2lo = __fdiv_rn(__fsub_rn(y, S), stepx);  w2hi = __fdiv_rn(y, stepx);
            has2 = (img == 0);
        } else {
            w1lo = __fdiv_rn(__fsub_rn(STOPF, y), stepx);
            w1hi = __fdiv_rn(__fadd_rn(__fsub_rn(STOPF, y), S), stepx);
            const float t = __fsub_rn(__fsub_rn(STOPF, x), STRIPF);
            w2lo = __fdiv_rn(t, stepx);
            w2hi = __fdiv_rn(__fadd_rn(t, S), stepx);
            has2 = (img == 0);
        }

        int aLo = 0, aHi = -1, bLo = 0, bHi = -1;
        {
            const int lo = (int)floorf(w1lo) - 2, hi = (int)ceilf(w1hi) + 2;
            if (lo <= 511) { aLo = max(lo, 0); aHi = min(511, max(hi, 0)); }
        }
        if (has2) {
            const int lo = (int)floorf(w2lo) - 2, hi = (int)ceilf(w2hi) + 2;
            if (lo <= 511) { bLo = max(lo, 0); bHi = min(511, max(hi, 0)); }
        }
        if (aHi < aLo) { aLo = bLo; aHi = bHi; bHi = -1; }
        if (bHi >= bLo) {
            if (bLo < aLo) { int t;
                t = aLo; aLo = bLo; bLo = t;  t = aHi; aHi = bHi; bHi = t; }
            if (bLo <= aHi + 1) { aHi = max(aHi, bHi); bHi = -1; }
        }

        short* qq = dim ? s_pV[k] : s_qH[k];
        float* dd = dim ? s_dvV[k] : s_dhH[k];
        int cnt = 0;
        #pragma unroll 1
        for (int sp = 0; sp < 2; ++sp) {
            const int lo = sp ? bLo : aLo, hi = sp ? bHi : aHi;
            if (hi < lo) continue;
            float prev = 0.f;
            for (int t = (lo == 0 ? 0 : lo - 1); t <= hi; ++t) {
                float f;
                if (dim == 0) {
                    const float px = __fmul_rn((float)t, stepx);
                    const float A  = __fsub_rn(__fadd_rn(px, S), x);
                    const float m  = img ? A : fminf(A, __fsub_rn(y, px));
                    f = fmaxf(fminf(S, m), 0.f);
                } else {
                    const float py = __fadd_rn(STOPF, __fmul_rn((float)t, stepy));
                    float m;
                    if (img) m = __fsub_rn(y, py);
                    else m = fminf(__fsub_rn(__fadd_rn(py, S), y),
                                   __fsub_rn(__fadd_rn(x, STRIPF), py));
                    f = fmaxf(fminf(S, m), 0.f);
                }
                if (t >= lo && f != prev && cnt < MAXD) {
                    qq[cnt] = (short)t;
                    dd[cnt] = dim ? __fmul_rn(__fsub_rn(f, prev), invA)
                                  : __fsub_rn(f, prev);
                    ++cnt;
                }
                prev = f;
            }
        }
        (dim ? s_cntV : s_cntH)[k] = cnt;
    }
    __syncthreads();

    // copy per-k tables to global
    for (int i = tid; i < 64 * MAXD; i += NTHREADS) {
        ((float*)g_dhH[bid])[i] = ((float*)s_dhH)[i];
        ((float*)g_dvV[bid])[i] = ((float*)s_dvV)[i];
    }
    for (int i = tid; i < (64 * MAXD) / 2; i += NTHREADS) {
        ((int*)g_qH[bid])[i] = ((int*)s_qH)[i];
        ((int*)g_pV[bid])[i] = ((int*)s_pV)[i];
    }
    if (tid < 64) {
        g_cntH[bid][tid] = s_cntH[tid];
        g_cntV[bid][tid] = s_cntV[tid];
    }
    // flatten hor entries
    if (tid == 0) {
        int s = 0;
        for (int k = 0; k < 64; ++k) { off[k] = s; s += s_cntH[k]; }
        off[64] = s;
        g_nH[bid] = s;
    }
    __syncthreads();
    if (tid < 64) {
        const int o = off[tid];
        const int c = s_cntH[tid];
        for (int j = 0; j < c; ++j) {
            g_fdh[bid][o + j] = s_dhH[tid][j];
            g_fq [bid][o + j] = s_qH[tid][j];
            g_fk [bid][o + j] = (short)tid;
        }
    }
}

// ---------------- main kernel: one CTA per 32-row slice ----------------
__global__ void __launch_bounds__(NTHREADS)
raster_kernel(float* __restrict__ out)
{
    const double PI_D   = 3.141592653589793238462643383279502884;
    const double SIDE_D = (PI_D * 0.5) / 512.0;
    const float  S      = (float)SIDE_D;
    const float  STRIPF = (float)(PI_D * 0.5);
    const float  STOPF  = (float)(PI_D * 0.5 - SIDE_D);
    const float  stepx  = __fdiv_rn(STOPF, 511.0f);
    const float  stepy  = __fdiv_rn(-STOPF, 511.0f);
    const float  invA   = (float)(1.0 / (SIDE_D * SIDE_D));
    (void)stepx;

    __shared__ __align__(16) float s_dhH[64][MAXD], s_dvV[64][MAXD];
    __shared__ __align__(16) float s_fdh[FLATCAP];
    __shared__ __align__(16) short s_qH[64][MAXD], s_pV[64][MAXD];
    __shared__ __align__(16) short s_fq[FLATCAP], s_fk[FLATCAP];
    __shared__ int s_cntH[64], s_cntV[64], s_nH;
    __shared__ __align__(16) float xs[64], ys[64];
    __shared__ __align__(16) float Rbuf[NW][512];
    __shared__ __align__(16) float vbuf[NW][64];

    const int tid     = threadIdx.x;
    const int bid     = blockIdx.x;
    const int imgslot = bid >> 4;     // 0..511
    const int slice   = bid & 15;     // 32-row slice
    const int img     = imgslot & 1;

    // zero R scratch
    {
        float4* r4 = (float4*)&Rbuf[0][0];
        #pragma unroll
        for (int i = 0; i < 4; ++i)
            r4[tid * 4 + i] = make_float4(0.f, 0.f, 0.f, 0.f);
    }
    // cooperative table load (L2-hot)
    for (int i = tid; i < 64 * MAXD; i += NTHREADS) {
        ((float*)s_dhH)[i] = ((const float*)g_dhH[imgslot])[i];
        ((float*)s_dvV)[i] = ((const float*)g_dvV[imgslot])[i];
    }
    for (int i = tid; i < (64 * MAXD) / 2; i += NTHREADS) {
        ((int*)s_qH)[i] = ((const int*)g_qH[imgslot])[i];
        ((int*)s_pV)[i] = ((const int*)g_pV[imgslot])[i];
    }
    for (int i = tid; i < FLATCAP; i += NTHREADS)
        s_fdh[i] = g_fdh[imgslot][i];
    for (int i = tid; i < FLATCAP / 2; i += NTHREADS) {
        ((int*)s_fq)[i] = ((const int*)g_fq[imgslot])[i];
        ((int*)s_fk)[i] = ((const int*)g_fk[imgslot])[i];
    }
    if (tid < 64) {
        s_cntH[tid] = g_cntH[imgslot][tid];
        s_cntV[tid] = g_cntV[imgslot][tid];
    }
    if (tid == 0) s_nH = g_nH[imgslot];
    // xs/ys needed for vert closed form; recompute from tables is not possible,
    // so reload endpoints from the prep tables' source arrays is avoided by
    // passing them through constant math: we reload from global inputs instead.
    __syncthreads();

    const int warp = tid >> 5;
    const int lane = tid & 31;
    const int p0   = (slice << 5) + warp * SEG;
    float* const R = Rbuf[warp];

    // v(p0, k) * invA via dv prefix is NOT used; closed form needs xs/ys.
    // Instead: v(p0,k) = sum of dv entries with p <= p0 (exact prefix of exact
    // diffs). cntV <= MAXD=8, so each lane reconstructs its own k's value(s).
    {
        float acc = 0.f;
        const int c = s_cntV[lane];
        #pragma unroll
        for (int j = 0; j < MAXD; ++j)
            if (j < c && s_pV[lane][j] <= p0) acc += s_dvV[lane][j];
        vbuf[warp][lane] = acc;                    // already scaled by invA
        if (!img) {
            float acc2 = 0.f;
            const int c2 = s_cntV[lane + 32];
            #pragma unroll
            for (int j = 0; j < MAXD; ++j)
                if (j < c2 && s_pV[lane + 32][j] <= p0) acc2 += s_dvV[lane + 32][j];
            vbuf[warp][lane + 32] = acc2;
        }
    }
    __syncwarp();

    // base row: parallel scatter over the flat (q,k,dh) list
    {
        const int nH = s_nH;
        for (int e = lane; e < nH; e += 32) {
            const float v = vbuf[warp][s_fk[e]];
            if (v != 0.f)
                atomicAdd(&R[s_fq[e]], v * s_fdh[e]);
        }
        __syncwarp();
    }

    // dv cursors: lane owns k0 = lane (and k1 = lane+32 for hf)
    const int k0 = lane, k1 = lane + 32;
    const int c0 = s_cntV[k0];
    const int c1 = (img == 0) ? s_cntV[k1] : 0;
    int cur0 = 0; while (cur0 < c0 && s_pV[k0][cur0] <= p0) ++cur0;
    int cur1 = 0; while (cur1 < c1 && s_pV[k1][cur1] <= p0) ++cur1;
    int np0 = (cur0 < c0) ? s_pV[k0][cur0] : (1 << 30);
    int np1 = (cur1 < c1) ? s_pV[k1][cur1] : (1 << 30);

    float O[16];
    #pragma unroll
    for (int i = 0; i < 16; ++i) O[i] = 0.f;

    float* orow = out + ((size_t)imgslot << 18) + ((size_t)p0 << 9);

    for (int p = p0; p < p0 + SEG; ++p) {
        bool doscan = (p == p0);
        if (p > p0) {
            const bool m0 = (np0 == p), m1 = (np1 == p);
            unsigned bal0 = __ballot_sync(0xFFFFFFFFu, m0);
            unsigned bal1 = __ballot_sync(0xFFFFFFFFu, m1);
            float dv0 = 0.f, dv1 = 0.f;
            if (m0) { dv0 = s_dvV[k0][cur0]; ++cur0;
                      np0 = (cur0 < c0) ? s_pV[k0][cur0] : (1 << 30); }
            if (m1) { dv1 = s_dvV[k1][cur1]; ++cur1;
                      np1 = (cur1 < c1) ? s_pV[k1][cur1] : (1 << 30); }
            if (bal0 | bal1) {
                doscan = true;
                while (bal0) {
                    const int src = __ffs(bal0) - 1; bal0 &= bal0 - 1;
                    const float dv = __shfl_sync(0xFFFFFFFFu, dv0, src);
                    if (lane < s_cntH[src]) {
                        const int q = s_qH[src][lane];
                        R[q] = __fmaf_rn(dv, s_dhH[src][lane], R[q]);
                    }
                    __syncwarp();
                }
                while (bal1) {
                    const int src = __ffs(bal1) - 1; bal1 &= bal1 - 1;
                    const float dv = __shfl_sync(0xFFFFFFFFu, dv1, src);
                    const int k = src + 32;
                    if (lane < s_cntH[k]) {
                        const int q = s_qH[k][lane];
                        R[q] = __fmaf_rn(dv, s_dhH[k][lane], R[q]);
                    }
                    __syncwarp();
                }
            }
        }
        if (doscan) {
            __syncwarp();
            float carry = 0.f;
            float4* r4 = (float4*)R;
            #pragma unroll
            for (int m = 0; m < 4; ++m) {
                float4 c = r4[m * 32 + lane];
                r4[m * 32 + lane] = make_float4(0.f, 0.f, 0.f, 0.f);  // clear for next row
                c.y += c.x; c.z += c.y; c.w += c.z;
                const float t = c.w;
                float incl = t;
                #pragma unroll
                for (int d = 1; d < 32; d <<= 1) {
                    const float s = __shfl_up_sync(0xFFFFFFFFu, incl, d);
                    if (lane >= d) incl += s;
                }
                const float add = incl - t + carry;
                O[4 * m + 0] += c.x + add;
                O[4 * m + 1] += c.y + add;
                O[4 * m + 2] += c.z + add;
                O[4 * m + 3] += c.w + add;
                carry += __shfl_sync(0xFFFFFFFFu, incl, 31);
            }
            __syncwarp();
        }
        // coalesced streaming row store (always)
        __stcs((float4*)(orow) + lane +  0, make_float4(O[0],  O[1],  O[2],  O[3]));
        __stcs((float4*)(orow) + lane + 32, make_float4(O[4],  O[5],  O[6],  O[7]));
        __stcs((float4*)(orow) + lane + 64, make_float4(O[8],  O[9],  O[10], O[11]));
        __stcs((float4*)(orow) + lane + 96, make_float4(O[12], O[13], O[14], O[15]));
        orow += 512;
    }
    (void)xs; (void)ys; (void)STRIPF; (void)STOPF; (void)S; (void)stepy; (void)invA;
}

extern "C" void kernel_launch(void* const* d_in, const int* in_sizes, int n_in,
                              void* d_out, int out_size)
{
    const float* iv0 = (const float*)d_in[0];   // intervals00: (256, 32, 2) f32
    const float* iv1 = (const float*)d_in[1];   // intervals01: (256, 32, 2) f32
    float* out = (float*)d_out;                 // (256, 2, 512, 512) f32
    (void)in_sizes; (void)n_in; (void)out_size;
    prep_kernel<<<512, NTHREADS>>>(iv0, iv1);
    raster_kernel<<<8192, NTHREADS>>>(out);
}